// round 2
// baseline (speedup 1.0000x reference)
#include <cuda_runtime.h>
#include <math.h>

// Fused blockwise-dequant GEMM: C[M,N] = X[M,K] * W[N,K]^T
// W[n,k] = (Q[n,k] - 127.5) / 127.5 * absmax[n, k/256]
//
// 128x128x16 tiles, 256 threads, 8x8 per-thread micro-tile,
// accumulators packed as f32x2 pairs driven by PTX fma.rn.f32x2
// (2 FMAs per issue slot on the fma pipe; bit-identical to scalar FFMA).

#define BM 128
#define BN 128
#define BK 16
#define TM 8
#define TN 8
#define THREADS 256

typedef unsigned long long ull;

__device__ __forceinline__ ull pack_dup(float a) {
    ull r;
    asm("mov.b64 %0, {%1, %1};" : "=l"(r) : "f"(a));
    return r;
}

__device__ __forceinline__ void fma2(ull& acc, ull a, ull b) {
    asm("fma.rn.f32x2 %0, %1, %2, %0;" : "+l"(acc) : "l"(a), "l"(b));
}

__device__ __forceinline__ void unpack2(ull v, float& lo, float& hi) {
    asm("mov.b64 {%0, %1}, %2;" : "=f"(lo), "=f"(hi) : "l"(v));
}

__global__ __launch_bounds__(THREADS, 2)
void dq_gemm_kernel(const float* __restrict__ X,
                    const int* __restrict__ Q,
                    const float* __restrict__ AM,
                    float* __restrict__ C,
                    int M, int N, int K) {
    // +4 padding keeps float4 alignment (132*4B = 528B, multiple of 16)
    // while breaking most store-phase bank conflicts.
    __shared__ float As[BK][BM + 4];   // X^T tile: As[k][m]
    __shared__ float Bs[BK][BN + 4];   // W^T tile: Bs[k][n]

    const int tid = threadIdx.x;
    const int tx = tid & 15;           // n-direction (0..15)
    const int ty = tid >> 4;           // m-direction (0..15)
    const int m0 = blockIdx.x * BM;
    const int n0 = blockIdx.y * BN;
    const int nblk = K >> 8;           // absmax blocks per row (K/256)

    ull acc[TM][TN / 2];
    #pragma unroll
    for (int i = 0; i < TM; i++)
        #pragma unroll
        for (int j = 0; j < TN / 2; j++)
            acc[i][j] = 0ull;

    for (int k0 = 0; k0 < K; k0 += BK) {
        const int amIdx = k0 >> 8;

        // ---- load X tile [BM, BK] -> As[k][m] (transposed) ----
        #pragma unroll
        for (int t = 0; t < 2; t++) {
            int idx = tid + t * THREADS;          // 0..511
            int row = idx >> 2;                   // 0..127
            int c   = (idx & 3) << 2;             // 0,4,8,12
            float4 v = *(const float4*)(X + (size_t)(m0 + row) * K + k0 + c);
            As[c + 0][row] = v.x;
            As[c + 1][row] = v.y;
            As[c + 2][row] = v.z;
            As[c + 3][row] = v.w;
        }

        // ---- load + dequant W tile [BN, BK] -> Bs[k][n] (transposed) ----
        #pragma unroll
        for (int t = 0; t < 2; t++) {
            int idx = tid + t * THREADS;
            int row = idx >> 2;                   // 0..127 (vocab row within tile)
            int c   = (idx & 3) << 2;
            int4 q = *(const int4*)(Q + (size_t)(n0 + row) * K + k0 + c);
            float s = __ldg(AM + (size_t)(n0 + row) * nblk + amIdx) * (1.0f / 127.5f);
            Bs[c + 0][row] = ((float)q.x - 127.5f) * s;
            Bs[c + 1][row] = ((float)q.y - 127.5f) * s;
            Bs[c + 2][row] = ((float)q.z - 127.5f) * s;
            Bs[c + 3][row] = ((float)q.w - 127.5f) * s;
        }

        __syncthreads();

        // ---- 8x8 micro-tile outer products, FFMA2 packed along n ----
        #pragma unroll
        for (int k = 0; k < BK; k++) {
            float4 a0 = *(const float4*)&As[k][ty * TM];
            float4 a1 = *(const float4*)&As[k][ty * TM + 4];
            const ull* bp = (const ull*)&Bs[k][tx * TN];
            ull b0 = bp[0], b1 = bp[1], b2 = bp[2], b3 = bp[3];

            ull ad[TM];
            ad[0] = pack_dup(a0.x); ad[1] = pack_dup(a0.y);
            ad[2] = pack_dup(a0.z); ad[3] = pack_dup(a0.w);
            ad[4] = pack_dup(a1.x); ad[5] = pack_dup(a1.y);
            ad[6] = pack_dup(a1.z); ad[7] = pack_dup(a1.w);

            #pragma unroll
            for (int i = 0; i < TM; i++) {
                fma2(acc[i][0], ad[i], b0);
                fma2(acc[i][1], ad[i], b1);
                fma2(acc[i][2], ad[i], b2);
                fma2(acc[i][3], ad[i], b3);
            }
        }

        __syncthreads();
    }

    // ---- epilogue: unpack pairs, vectorized float4 stores ----
    #pragma unroll
    for (int i = 0; i < TM; i++) {
        float o[8];
        unpack2(acc[i][0], o[0], o[1]);
        unpack2(acc[i][1], o[2], o[3]);
        unpack2(acc[i][2], o[4], o[5]);
        unpack2(acc[i][3], o[6], o[7]);
        float4* cp = (float4*)(C + (size_t)(m0 + ty * TM + i) * N + n0 + tx * TN);
        cp[0] = make_float4(o[0], o[1], o[2], o[3]);
        cp[1] = make_float4(o[4], o[5], o[6], o[7]);
    }
}

extern "C" void kernel_launch(void* const* d_in, const int* in_sizes, int n_in,
                              void* d_out, int out_size) {
    const float* X  = (const float*)d_in[0];   // x: [B,S,D] f32 -> [M,K]
    const int*   Q  = (const int*)d_in[1];     // q_weight: [V,D] int32 -> [N,K]
    const float* AM = (const float*)d_in[2];   // absmax: [V, D/256] f32

    // Derive dims: s0 = M*K, s1 = N*K, out = M*N  =>  K = sqrt(s0*s1/out)
    double s0 = (double)in_sizes[0];
    double s1 = (double)in_sizes[1];
    double so = (double)out_size;
    int K = (int)(sqrt(s0 * s1 / so) + 0.5);
    int M = (int)(s0 / K + 0.5);
    int N = (int)(s1 / K + 0.5);

    // Grid ordered (m-tiles, n-tiles): a wave spans all m-tiles of a few
    // n-stripes, so x (32 MB) stays L2-resident while q_weight streams.
    dim3 grid(M / BM, N / BN);
    dq_gemm_kernel<<<grid, THREADS>>>(X, Q, AM, (float*)d_out, M, N, K);
}